// round 17
// baseline (speedup 1.0000x reference)
#include <cuda_runtime.h>

// Problem shape (fixed by the dataset)
#define TT 4096
#define NB 16
#define CC 512
#define NC (NB * CC)            // 8192 columns
#define NC4 (NC / 4)            // 2048 float4 columns
#define TOTAL (TT * NC)         // 33,554,432 floats for new_x

#define CHUNK 16                // rows per thread
#define NCH (TT / CHUNK)        // 256 chunks
#define SUM_BLOCKS ((NCH * NC4) / 256)   // 2048
#define RCP_BLOCKS ((TT * NB) / 256)     // 256
#define SCAN_BLOCKS (NC4 / 8)            // 256 (8 warps/block, warp per col4)

// Static scratch (no allocations; zero-init counters self-reset each launch)
__device__ float4 g_agg[NCH * NC4];    // 8 MB: per-(chunk, col4) sums
__device__ float4 g_base[NCH * NC4];   // 8 MB: seeded exclusive bases
__device__ float  g_rcp[TT * NB];      // 256 KB: 1/(t+1+len_n), [t][n]
__device__ int    g_ctr;               // sum-blocks-done counter
__device__ int    g_ctr2;              // scan-blocks-done counter (for reset)

__device__ __forceinline__ float4 f4add(float4 a, float4 b) {
    return make_float4(a.x + b.x, a.y + b.y, a.z + b.z, a.w + b.w);
}
__device__ __forceinline__ float4 f4shfl_up(float4 v, int off) {
    v.x = __shfl_up_sync(0xffffffffu, v.x, off);
    v.y = __shfl_up_sync(0xffffffffu, v.y, off);
    v.z = __shfl_up_sync(0xffffffffu, v.z, off);
    v.w = __shfl_up_sync(0xffffffffu, v.w, off);
    return v;
}

// kA: three roles by bid range.
//  [0, SUM):          per-(chunk,col4) partial sums (plain loads, ascending)
//  [SUM, SUM+RCP):    reciprocal table
//  [SUM+RCP, ...):    base scan — dispatched LAST, spins until all sum blocks
//                     publish, then warp-shfl scans L2-hot g_agg into g_base.
//                     Counters self-reset so graph replays are deterministic.
__global__ void __launch_bounds__(256)
kA(const float4* __restrict__ x4, const int* __restrict__ cached_len,
   const float4* __restrict__ avg4) {
    int bid = blockIdx.x, tid = threadIdx.x;

    if (bid < SUM_BLOCKS) {
        int idx = bid * 256 + tid;                 // 0 .. NCH*NC4-1
        int nc4 = idx & (NC4 - 1);
        int gc = idx >> 11;
        const float4* p = x4 + (size_t)gc * CHUNK * NC4 + nc4;
        float4 s = make_float4(0.f, 0.f, 0.f, 0.f);
#pragma unroll
        for (int i = 0; i < CHUNK; i++) s = f4add(s, p[(size_t)i * NC4]);
        g_agg[gc * NC4 + nc4] = s;
        __threadfence();                           // release my agg store
        __syncthreads();                           // whole block's stores fenced
        if (tid == 0) atomicAdd(&g_ctr, 1);
        return;
    }

    if (bid < SUM_BLOCKS + RCP_BLOCKS) {
        int idx = (bid - SUM_BLOCKS) * 256 + tid;  // 0 .. TT*NB-1
        int n = idx & (NB - 1);
        int t = idx >> 4;
        g_rcp[idx] = 1.0f / ((float)(t + 1) + (float)cached_len[n]);
        return;
    }

    // ── Scan role ──
    if (tid == 0) {
        volatile int* c = &g_ctr;
        while (*c != SUM_BLOCKS) __nanosleep(64);
    }
    __syncthreads();
    __threadfence();                               // acquire g_agg

    int col4 = (bid - SUM_BLOCKS - RCP_BLOCKS) * 8 + (tid >> 5);   // 0..NC4-1
    int lane = tid & 31;

    float lenf = (float)cached_len[col4 >> 7];
    float4 sa = avg4[col4];
    float4 seed = make_float4(sa.x * lenf, sa.y * lenf, sa.z * lenf, sa.w * lenf);

    float4 a[8];
#pragma unroll
    for (int k = 0; k < 8; k++)
        a[k] = g_agg[(8 * lane + k) * NC4 + col4];

    float4 tot = a[0];
#pragma unroll
    for (int k = 1; k < 8; k++) tot = f4add(tot, a[k]);

    float4 incl = tot;
#pragma unroll
    for (int off = 1; off < 32; off <<= 1) {
        float4 up = f4shfl_up(incl, off);
        if (lane >= off) incl = f4add(incl, up);
    }
    float4 excl = f4shfl_up(incl, 1);
    if (lane == 0) excl = make_float4(0.f, 0.f, 0.f, 0.f);

    float4 run = f4add(seed, excl);
#pragma unroll
    for (int k = 0; k < 8; k++) {
        g_base[(8 * lane + k) * NC4 + col4] = run;
        run = f4add(run, a[k]);
    }

    // Self-reset counters once every scan block is done (graph-replay safe).
    __syncthreads();
    if (tid == 0) {
        int done = atomicAdd(&g_ctr2, 1);
        if (done == SCAN_BLOCKS - 1) {
            g_ctr = 0;
            g_ctr2 = 0;
            __threadfence();
        }
    }
}

// kB: final scan, chunk-DESCENDING dispatch (consumes kA's L2-hot high
// chunks first); plain loads, evict-first stores.
__global__ void __launch_bounds__(256)
kB(const float4* __restrict__ x4, const int* __restrict__ cached_len,
   float4* __restrict__ out4, int extras) {
    int idx = blockIdx.x * 256 + threadIdx.x;      // 0 .. NCH*NC4-1
    int nc4 = idx & (NC4 - 1);
    int gc = (NCH - 1) - (idx >> 11);              // reversed chunk order
    int n = nc4 >> 7;                              // warp-uniform

    float4 run = g_base[gc * NC4 + nc4];
    const float4* px = x4   + (size_t)gc * CHUNK * NC4 + nc4;
    float4*       po = out4 + (size_t)gc * CHUNK * NC4 + nc4;
    const float*  pr = g_rcp + (size_t)gc * CHUNK * NB + n;

    float4 last = make_float4(0.f, 0.f, 0.f, 0.f);
#pragma unroll
    for (int i = 0; i < CHUNK; i++) {
        float4 v = px[(size_t)i * NC4];            // plain load (proven best)
        run = f4add(run, v);
        float r = pr[(size_t)i * NB];
        last.x = run.x * r; last.y = run.y * r;
        last.z = run.z * r; last.w = run.w * r;
        __stcs(po + (size_t)i * NC4, last);        // evict-first store
    }

    if (extras) {
        // Tuple order: [new_x | new_cached_len (as float) | new_cached_avg]
        if (gc == NCH - 1)
            out4[(TOTAL + NB) / 4 + nc4] = last;   // new_x[T-1]
        if (idx < NB) {
            float* outf = (float*)out4;
            outf[TOTAL + idx] = (float)(cached_len[idx] + TT);
        }
    }
}

extern "C" void kernel_launch(void* const* d_in, const int* in_sizes, int n_in,
                              void* d_out, int out_size) {
    const float4* x4         = (const float4*)d_in[0];   // (T, N, C)
    const int*    cached_len = (const int*)d_in[1];      // (N,)
    const float4* avg4       = (const float4*)d_in[2];   // (N, C)
    float4* out4 = (float4*)d_out;

    int extras = (out_size >= TOTAL + NB + NC) ? 1 : 0;

    kA<<<SUM_BLOCKS + RCP_BLOCKS + SCAN_BLOCKS, 256>>>(x4, cached_len, avg4);
    kB<<<SUM_BLOCKS, 256>>>(x4, cached_len, out4, extras);
}